// round 10
// baseline (speedup 1.0000x reference)
#include <cuda_runtime.h>
#include <cstdint>

// CSpace resonator bank as 1st-order complex IIR, split-scan over time slices.
// 1024 sequences x 25 slices of 1920 samples; warp per slice.
// kprep: per-channel constant tables (double precision, once).
// Kernel A: slice totals via real-input weighted sums + deferred reduction.
// Kernel C: fold entry + scan + serial replay, streaming stores.

#define TT 48000
#define CC 64
#define BB 8
#define KLEN 24000
#define NSLICE 25
#define SLEN 1920
#define NITERS 15           // 15 * 128 = 1920
#define NSEQ (BB * CC * 2)  // 1024
#define NWORK (NSEQ * NSLICE) // 25600
#define WPB 8               // warps per block
#define NBLK (NWORK / WPB)  // 3200

__device__ float2 g_tot[NWORK];
// table layout (32 floats per channel):
// [0..7]  e^1..e^4 (re,im)
// [8..17] A_k = E4^(2^k), k=0..4  (E4,E8,E16,E32,E64)
// [18..19] E128   [20..21] E1920   [22..23] g
// [24..31] w0..w3  (w_k = g * e^(3-k))
__device__ float g_ctab[CC][32];

__device__ __forceinline__ void cmulD(double& ar, double& ai, double br, double bi) {
    double t = ar * br - ai * bi;
    ai = ar * bi + ai * br;
    ar = t;
}

__global__ void kprep(const float* __restrict__ kre, const float* __restrict__ kim) {
    int c = threadIdx.x;
    if (c >= CC) return;
    double k0r = kre[c * KLEN + 0], k0i = kim[c * KLEN + 0];
    double k1r = kre[c * KLEN + 1], k1i = kim[c * KLEN + 1];
    double inv = 1.0 / (k0r * k0r + k0i * k0i);
    double er = (k1r * k0r + k1i * k0i) * inv;
    double ei = (k1i * k0r - k1r * k0i) * inv;

    double e2r = er, e2i = ei;  cmulD(e2r, e2i, er, ei);
    double e3r = e2r, e3i = e2i; cmulD(e3r, e3i, er, ei);
    double e4r = e2r, e4i = e2i; cmulD(e4r, e4i, e2r, e2i);

    double Ar[6], Ai[6];
    Ar[0] = e4r; Ai[0] = e4i;
    #pragma unroll
    for (int k = 1; k < 6; ++k) { Ar[k] = Ar[k-1]; Ai[k] = Ai[k-1]; cmulD(Ar[k], Ai[k], Ar[k-1], Ai[k-1]); }
    double Cr[4], Ci[4];
    Cr[0] = Ar[5]; Ci[0] = Ai[5];
    #pragma unroll
    for (int k = 1; k < 4; ++k) { Cr[k] = Cr[k-1]; Ci[k] = Ci[k-1]; cmulD(Cr[k], Ci[k], Cr[k-1], Ci[k-1]); }
    double Fr = Cr[0], Fi = Ci[0];
    cmulD(Fr, Fi, Cr[1], Ci[1]);
    cmulD(Fr, Fi, Cr[2], Ci[2]);
    cmulD(Fr, Fi, Cr[3], Ci[3]);

    // weights w_k = g * e^(3-k)
    double w3r = k0r, w3i = k0i;
    double w2r = w3r, w2i = w3i; cmulD(w2r, w2i, er, ei);
    double w1r = w3r, w1i = w3i; cmulD(w1r, w1i, e2r, e2i);
    double w0r = w3r, w0i = w3i; cmulD(w0r, w0i, e3r, e3i);

    float* t = g_ctab[c];
    t[0] = (float)er;  t[1] = (float)ei;
    t[2] = (float)e2r; t[3] = (float)e2i;
    t[4] = (float)e3r; t[5] = (float)e3i;
    t[6] = (float)e4r; t[7] = (float)e4i;
    #pragma unroll
    for (int k = 0; k < 5; ++k) { t[8 + 2*k] = (float)Ar[k]; t[9 + 2*k] = (float)Ai[k]; }
    t[18] = (float)Ar[5]; t[19] = (float)Ai[5];
    t[20] = (float)Fr;    t[21] = (float)Fi;
    t[22] = (float)k0r;   t[23] = (float)k0i;
    t[24] = (float)w0r;   t[25] = (float)w0i;
    t[26] = (float)w1r;   t[27] = (float)w1i;
    t[28] = (float)w2r;   t[29] = (float)w2i;
    t[30] = (float)w3r;   t[31] = (float)w3i;
}

// ---------------- Kernel A: slice totals ----------------
template <bool REV>
__device__ __forceinline__ void sliceA(const float* __restrict__ x, int j, int lane,
                                       const float* __restrict__ tb, int W)
{
    const unsigned FULL = 0xFFFFFFFFu;
    const float e128r = tb[18], e128i = tb[19];
    const float w0r = tb[24], w0i = tb[25];
    const float w1r = tb[26], w1i = tb[27];
    const float w2r = tb[28], w2i = tb[29];
    const float w3r = tb[30], w3i = tb[31];

    // lane-local accumulator: A = E128*A + y_i  (y_i = weighted 4-sample partial)
    float Acr = 0.f, Aci = 0.f;
    #pragma unroll 5
    for (int i = 0; i < NITERS; ++i) {
        int n0 = j * SLEN + i * 128 + lane * 4;
        float4 v = REV ? *reinterpret_cast<const float4*>(x + (TT - 4 - n0))
                       : *reinterpret_cast<const float4*>(x + n0);
        float x0, x1, x2, x3;
        if (!REV) { x0=v.x; x1=v.y; x2=v.z; x3=v.w; }
        else      { x0=v.w; x1=v.z; x2=v.y; x3=v.x; }

        float yr = w0r*x0 + w1r*x1 + w2r*x2 + w3r*x3;
        float yi = w0i*x0 + w1i*x1 + w2i*x2 + w3i*x3;

        float nAr = yr + e128r*Acr - e128i*Aci;
        float nAi = yi + e128r*Aci + e128i*Acr;
        Acr = nAr; Aci = nAi;
    }

    // weight = E4^(31-lane); one butterfly reduction of w*A
    float wr = 1.f, wi = 0.f;
    {
        int p = 31 - lane;
        #pragma unroll
        for (int k = 0; k < 5; ++k)
            if ((p >> k) & 1) {
                float ar = tb[8 + 2*k], ai = tb[9 + 2*k];
                float nr = wr*ar - wi*ai, ni = wr*ai + wi*ar;
                wr = nr; wi = ni;
            }
    }
    float sr = wr*Acr - wi*Aci;
    float si = wr*Aci + wi*Acr;
    #pragma unroll
    for (int d = 16; d >= 1; d >>= 1) {
        sr += __shfl_xor_sync(FULL, sr, d);
        si += __shfl_xor_sync(FULL, si, d);
    }
    if (lane == 0) g_tot[W] = make_float2(sr, si);
}

__global__ void __launch_bounds__(WPB * 32)
kA(const float* __restrict__ audio)
{
    int lane = threadIdx.x & 31;
    int W = blockIdx.x * WPB + (threadIdx.x >> 5);
    int s = W / NSLICE;
    int j = W - s * NSLICE;
    int dir = s & 1, c = (s >> 1) & 63, b = s >> 7;

    const float* tb = g_ctab[c];
    const float* x = audio + (size_t)b * TT;
    if (dir == 0) sliceA<false>(x, j, lane, tb, W);
    else          sliceA<true >(x, j, lane, tb, W);
}

// ---------------- Kernel C: outputs ----------------
__device__ __forceinline__ void st_cs4(float* p, float4 v) {
    asm volatile("st.global.cs.v4.f32 [%0], {%1,%2,%3,%4};"
                 :: "l"(p), "f"(v.x), "f"(v.y), "f"(v.z), "f"(v.w) : "memory");
}

template <bool REV>
__device__ __forceinline__ void sliceC(const float* __restrict__ x,
                                       float* __restrict__ out_re,
                                       float* __restrict__ out_im,
                                       int s, int j, int lane,
                                       const float* __restrict__ tb)
{
    const unsigned FULL = 0xFFFFFFFFu;
    const float er  = tb[0],  eic = tb[1];
    const float a0r = tb[8],  a0i = tb[9];
    const float a1r = tb[10], a1i = tb[11];
    const float a2r = tb[12], a2i = tb[13];
    const float a3r = tb[14], a3i = tb[15];
    const float a4r = tb[16], a4i = tb[17];
    const float e128r = tb[18], e128i = tb[19];
    const float f19r  = tb[20], f19i  = tb[21];
    const float gr = tb[22], gi = tb[23];
    const float w0r = tb[24], w0i = tb[25];
    const float w1r = tb[26], w1i = tb[27];
    const float w2r = tb[28], w2i = tb[29];
    const float w3r = tb[30], w3i = tb[31];

    // q = E4^lane
    float qr = 1.f, qi = 0.f;
    #pragma unroll
    for (int k = 0; k < 5; ++k)
        if ((lane >> k) & 1) {
            float ar = tb[8 + 2*k], ai = tb[9 + 2*k];
            float nr = qr*ar - qi*ai, ni = qr*ai + qi*ar;
            qr = nr; qi = ni;
        }

    // fold predecessor slice totals -> entry state (uniform loads, all lanes)
    float inr = 0.f, ini = 0.f;
    const float2* tot = &g_tot[s * NSLICE];
    for (int t = 0; t < j; ++t) {
        float2 v = tot[t];
        float nr = v.x + f19r*inr - f19i*ini;
        float ni = v.y + f19r*ini + f19i*inr;
        inr = nr; ini = ni;
    }

    #pragma unroll 3
    for (int i = 0; i < NITERS; ++i) {
        int n0 = j * SLEN + i * 128 + lane * 4;
        float4 v = REV ? *reinterpret_cast<const float4*>(x + (TT - 4 - n0))
                       : *reinterpret_cast<const float4*>(x + n0);
        float x0, x1, x2, x3;
        if (!REV) { x0=v.x; x1=v.y; x2=v.z; x3=v.w; }
        else      { x0=v.w; x1=v.z; x2=v.y; x3=v.x; }

        // 4-sample partial from zero state via real-input weights
        float c4r = w0r*x0 + w1r*x1 + w2r*x2 + w3r*x3;
        float c4i = w0i*x0 + w1i*x1 + w2i*x2 + w3i*x3;

        // warp inclusive scan of c4 with ratio E4
        float sr = c4r, si = c4i;
        { float ur=__shfl_up_sync(FULL,sr,1),  ui=__shfl_up_sync(FULL,si,1);
          if (lane>=1)  { sr += a0r*ur - a0i*ui; si += a0r*ui + a0i*ur; } }
        { float ur=__shfl_up_sync(FULL,sr,2),  ui=__shfl_up_sync(FULL,si,2);
          if (lane>=2)  { sr += a1r*ur - a1i*ui; si += a1r*ui + a1i*ur; } }
        { float ur=__shfl_up_sync(FULL,sr,4),  ui=__shfl_up_sync(FULL,si,4);
          if (lane>=4)  { sr += a2r*ur - a2i*ui; si += a2r*ui + a2i*ur; } }
        { float ur=__shfl_up_sync(FULL,sr,8),  ui=__shfl_up_sync(FULL,si,8);
          if (lane>=8)  { sr += a3r*ur - a3i*ui; si += a3r*ui + a3i*ur; } }
        { float ur=__shfl_up_sync(FULL,sr,16), ui=__shfl_up_sync(FULL,si,16);
          if (lane>=16) { sr += a4r*ur - a4i*ui; si += a4r*ui + a4i*ur; } }

        float hr = __shfl_up_sync(FULL, sr, 1);
        float hi = __shfl_up_sync(FULL, si, 1);
        if (lane == 0) { hr = 0.f; hi = 0.f; }

        // lane entry z = h + q*in
        float zr = hr + qr*inr - qi*ini;
        float zi = hi + qr*ini + qi*inr;

        // serial replay producing outputs: o = e*o + g*x
        float o1r = er*zr  - eic*zi  + gr*x0, o1i = er*zi  + eic*zr  + gi*x0;
        float o2r = er*o1r - eic*o1i + gr*x1, o2i = er*o1i + eic*o1r + gi*x1;
        float o3r = er*o2r - eic*o2i + gr*x2, o3i = er*o2i + eic*o2r + gi*x2;
        float o4r = er*o3r - eic*o3i + gr*x3, o4i = er*o3i + eic*o3r + gi*x3;

        if (!REV) {
            st_cs4(out_re + n0, make_float4(o1r,o2r,o3r,o4r));
            st_cs4(out_im + n0, make_float4(o1i,o2i,o3i,o4i));
        } else {
            st_cs4(out_re + (TT - 4 - n0), make_float4(o4r,o3r,o2r,o1r));
            st_cs4(out_im + (TT - 4 - n0), make_float4(o4i,o3i,o2i,o1i));
        }

        // advance slice-entry state: in = T + E128*in  (T = inclusive total, lane 31)
        float Tr = __shfl_sync(FULL, sr, 31);
        float Ti = __shfl_sync(FULL, si, 31);
        float nr = Tr + e128r*inr - e128i*ini;
        float ni = Ti + e128r*ini + e128i*inr;
        inr = nr; ini = ni;
    }
}

__global__ void __launch_bounds__(WPB * 32)
kC(const float* __restrict__ audio, float* __restrict__ out)
{
    int lane = threadIdx.x & 31;
    int W = blockIdx.x * WPB + (threadIdx.x >> 5);
    int s = W / NSLICE;
    int j = W - s * NSLICE;
    int dir = s & 1, c = (s >> 1) & 63, b = s >> 7;

    const float* tb = g_ctab[c];
    const float* x = audio + (size_t)b * TT;
    float* base = out + (size_t)b * 4 * CC * TT;

    if (dir == 0) {
        sliceC<false>(x, base + (size_t)c * TT, base + (size_t)(CC + c) * TT,
                      s, j, lane, tb);
    } else {
        sliceC<true >(x, base + (size_t)(2*CC + c) * TT, base + (size_t)(3*CC + c) * TT,
                      s, j, lane, tb);
    }
}

extern "C" void kernel_launch(void* const* d_in, const int* in_sizes, int n_in,
                              void* d_out, int out_size)
{
    const float* audio = (const float*)d_in[0];
    const float* kre   = (const float*)d_in[1];
    const float* kim   = (const float*)d_in[2];
    float* out = (float*)d_out;
    (void)in_sizes; (void)n_in; (void)out_size;

    kprep<<<1, 64>>>(kre, kim);
    kA<<<NBLK, WPB * 32>>>(audio);
    kC<<<NBLK, WPB * 32>>>(audio, out);
}

// round 11
// speedup vs baseline: 1.5856x; 1.5856x over previous
#include <cuda_runtime.h>
#include <cstdint>

// CSpace resonator bank as 1st-order complex IIR, split-scan over time slices.
// 1024 sequences x 25 slices of 1920 samples; warp per slice.
// kprep: per-channel constant tables (double precision, once).
// Kernel A: slice totals via real-input weighted sums + deferred reduction.
// Kernel C (R8 form): fold entry + scan + independent reconstruction, streaming stores.

#define TT 48000
#define CC 64
#define BB 8
#define KLEN 24000
#define NSLICE 25
#define SLEN 1920
#define NITERS 15           // 15 * 128 = 1920
#define NSEQ (BB * CC * 2)  // 1024
#define NWORK (NSEQ * NSLICE) // 25600
#define WPB 8               // warps per block
#define NBLK (NWORK / WPB)  // 3200

__device__ float2 g_tot[NWORK];
// table layout (32 floats per channel):
// [0..7]  e^1..e^4 (re,im)
// [8..17] A_k = E4^(2^k), k=0..4  (E4,E8,E16,E32,E64)
// [18..19] E128   [20..21] E1920   [22..23] g
// [24..31] w0..w3  (w_k = g * e^(3-k))
__device__ float g_ctab[CC][32];

__device__ __forceinline__ void cmulD(double& ar, double& ai, double br, double bi) {
    double t = ar * br - ai * bi;
    ai = ar * bi + ai * br;
    ar = t;
}

__global__ void kprep(const float* __restrict__ kre, const float* __restrict__ kim) {
    int c = threadIdx.x;
    if (c >= CC) return;
    double k0r = kre[c * KLEN + 0], k0i = kim[c * KLEN + 0];
    double k1r = kre[c * KLEN + 1], k1i = kim[c * KLEN + 1];
    double inv = 1.0 / (k0r * k0r + k0i * k0i);
    double er = (k1r * k0r + k1i * k0i) * inv;
    double ei = (k1i * k0r - k1r * k0i) * inv;

    double e2r = er, e2i = ei;  cmulD(e2r, e2i, er, ei);
    double e3r = e2r, e3i = e2i; cmulD(e3r, e3i, er, ei);
    double e4r = e2r, e4i = e2i; cmulD(e4r, e4i, e2r, e2i);

    double Ar[6], Ai[6];
    Ar[0] = e4r; Ai[0] = e4i;
    #pragma unroll
    for (int k = 1; k < 6; ++k) { Ar[k] = Ar[k-1]; Ai[k] = Ai[k-1]; cmulD(Ar[k], Ai[k], Ar[k-1], Ai[k-1]); }
    double Cr[4], Ci[4];
    Cr[0] = Ar[5]; Ci[0] = Ai[5];
    #pragma unroll
    for (int k = 1; k < 4; ++k) { Cr[k] = Cr[k-1]; Ci[k] = Ci[k-1]; cmulD(Cr[k], Ci[k], Cr[k-1], Ci[k-1]); }
    double Fr = Cr[0], Fi = Ci[0];
    cmulD(Fr, Fi, Cr[1], Ci[1]);
    cmulD(Fr, Fi, Cr[2], Ci[2]);
    cmulD(Fr, Fi, Cr[3], Ci[3]);

    // weights w_k = g * e^(3-k)
    double w3r = k0r, w3i = k0i;
    double w2r = w3r, w2i = w3i; cmulD(w2r, w2i, er, ei);
    double w1r = w3r, w1i = w3i; cmulD(w1r, w1i, e2r, e2i);
    double w0r = w3r, w0i = w3i; cmulD(w0r, w0i, e3r, e3i);

    float* t = g_ctab[c];
    t[0] = (float)er;  t[1] = (float)ei;
    t[2] = (float)e2r; t[3] = (float)e2i;
    t[4] = (float)e3r; t[5] = (float)e3i;
    t[6] = (float)e4r; t[7] = (float)e4i;
    #pragma unroll
    for (int k = 0; k < 5; ++k) { t[8 + 2*k] = (float)Ar[k]; t[9 + 2*k] = (float)Ai[k]; }
    t[18] = (float)Ar[5]; t[19] = (float)Ai[5];
    t[20] = (float)Fr;    t[21] = (float)Fi;
    t[22] = (float)k0r;   t[23] = (float)k0i;
    t[24] = (float)w0r;   t[25] = (float)w0i;
    t[26] = (float)w1r;   t[27] = (float)w1i;
    t[28] = (float)w2r;   t[29] = (float)w2i;
    t[30] = (float)w3r;   t[31] = (float)w3i;
}

// ---------------- Kernel A: slice totals (weighted partial + deferred reduction) ----------------
template <bool REV>
__device__ __forceinline__ void sliceA(const float* __restrict__ x, int j, int lane,
                                       const float* __restrict__ tb, int W)
{
    const unsigned FULL = 0xFFFFFFFFu;
    const float e128r = tb[18], e128i = tb[19];
    const float w0r = tb[24], w0i = tb[25];
    const float w1r = tb[26], w1i = tb[27];
    const float w2r = tb[28], w2i = tb[29];
    const float w3r = tb[30], w3i = tb[31];

    // lane-local accumulator: A = E128*A + y_i  (y_i = weighted 4-sample partial)
    float Acr = 0.f, Aci = 0.f;
    #pragma unroll 5
    for (int i = 0; i < NITERS; ++i) {
        int n0 = j * SLEN + i * 128 + lane * 4;
        float4 v = REV ? *reinterpret_cast<const float4*>(x + (TT - 4 - n0))
                       : *reinterpret_cast<const float4*>(x + n0);
        float x0, x1, x2, x3;
        if (!REV) { x0=v.x; x1=v.y; x2=v.z; x3=v.w; }
        else      { x0=v.w; x1=v.z; x2=v.y; x3=v.x; }

        float yr = w0r*x0 + w1r*x1 + w2r*x2 + w3r*x3;
        float yi = w0i*x0 + w1i*x1 + w2i*x2 + w3i*x3;

        float nAr = yr + e128r*Acr - e128i*Aci;
        float nAi = yi + e128r*Aci + e128i*Acr;
        Acr = nAr; Aci = nAi;
    }

    // weight = E4^(31-lane); one butterfly reduction of w*A
    float wr = 1.f, wi = 0.f;
    {
        int p = 31 - lane;
        #pragma unroll
        for (int k = 0; k < 5; ++k)
            if ((p >> k) & 1) {
                float ar = tb[8 + 2*k], ai = tb[9 + 2*k];
                float nr = wr*ar - wi*ai, ni = wr*ai + wi*ar;
                wr = nr; wi = ni;
            }
    }
    float sr = wr*Acr - wi*Aci;
    float si = wr*Aci + wi*Acr;
    #pragma unroll
    for (int d = 16; d >= 1; d >>= 1) {
        sr += __shfl_xor_sync(FULL, sr, d);
        si += __shfl_xor_sync(FULL, si, d);
    }
    if (lane == 0) g_tot[W] = make_float2(sr, si);
}

__global__ void __launch_bounds__(WPB * 32)
kA(const float* __restrict__ audio)
{
    int lane = threadIdx.x & 31;
    int W = blockIdx.x * WPB + (threadIdx.x >> 5);
    int s = W / NSLICE;
    int j = W - s * NSLICE;
    int dir = s & 1, c = (s >> 1) & 63, b = s >> 7;

    const float* tb = g_ctab[c];
    const float* x = audio + (size_t)b * TT;
    if (dir == 0) sliceA<false>(x, j, lane, tb, W);
    else          sliceA<true >(x, j, lane, tb, W);
}

// ---------------- Kernel C: outputs (R8 form) ----------------
__device__ __forceinline__ void st_cs4(float* p, float4 v) {
    asm volatile("st.global.cs.v4.f32 [%0], {%1,%2,%3,%4};"
                 :: "l"(p), "f"(v.x), "f"(v.y), "f"(v.z), "f"(v.w) : "memory");
}

template <bool REV>
__device__ __forceinline__ void sliceC(const float* __restrict__ x,
                                       float* __restrict__ out_re,
                                       float* __restrict__ out_im,
                                       int s, int j, int lane,
                                       const float* __restrict__ tb)
{
    const unsigned FULL = 0xFFFFFFFFu;
    const float er  = tb[0],  eic = tb[1];
    const float e2r = tb[2],  e2i = tb[3];
    const float e3r = tb[4],  e3i = tb[5];
    const float e4r = tb[6],  e4i = tb[7];
    const float a0r = tb[8],  a0i = tb[9];
    const float a1r = tb[10], a1i = tb[11];
    const float a2r = tb[12], a2i = tb[13];
    const float a3r = tb[14], a3i = tb[15];
    const float a4r = tb[16], a4i = tb[17];
    const float e128r = tb[18], e128i = tb[19];
    const float f19r  = tb[20], f19i  = tb[21];
    const float gr = tb[22], gi = tb[23];

    // q = E4^lane
    float qr = 1.f, qi = 0.f;
    #pragma unroll
    for (int k = 0; k < 5; ++k)
        if ((lane >> k) & 1) {
            float ar = tb[8 + 2*k], ai = tb[9 + 2*k];
            float nr = qr*ar - qi*ai, ni = qr*ai + qi*ar;
            qr = nr; qi = ni;
        }

    // fold predecessor slice totals -> entry state (uniform loads, all lanes)
    float inr = 0.f, ini = 0.f;
    const float2* tot = &g_tot[s * NSLICE];
    for (int t = 0; t < j; ++t) {
        float2 v = tot[t];
        float nr = v.x + f19r*inr - f19i*ini;
        float ni = v.y + f19r*ini + f19i*inr;
        inr = nr; ini = ni;
    }

    #pragma unroll 3
    for (int i = 0; i < NITERS; ++i) {
        int n0 = j * SLEN + i * 128 + lane * 4;
        float4 v = REV ? *reinterpret_cast<const float4*>(x + (TT - 4 - n0))
                       : *reinterpret_cast<const float4*>(x + n0);
        float x0, x1, x2, x3;
        if (!REV) { x0=v.x; x1=v.y; x2=v.z; x3=v.w; }
        else      { x0=v.w; x1=v.z; x2=v.y; x3=v.x; }

        // local partials from zero (kept for output reconstruction)
        float c1r = gr*x0, c1i = gi*x0;
        float c2r = er*c1r - eic*c1i + gr*x1, c2i = er*c1i + eic*c1r + gi*x1;
        float c3r = er*c2r - eic*c2i + gr*x2, c3i = er*c2i + eic*c2r + gi*x2;
        float c4r = er*c3r - eic*c3i + gr*x3, c4i = er*c3i + eic*c3r + gi*x3;

        // warp inclusive scan of c4 with ratio E4
        float sr = c4r, si = c4i;
        { float ur=__shfl_up_sync(FULL,sr,1),  ui=__shfl_up_sync(FULL,si,1);
          if (lane>=1)  { sr += a0r*ur - a0i*ui; si += a0r*ui + a0i*ur; } }
        { float ur=__shfl_up_sync(FULL,sr,2),  ui=__shfl_up_sync(FULL,si,2);
          if (lane>=2)  { sr += a1r*ur - a1i*ui; si += a1r*ui + a1i*ur; } }
        { float ur=__shfl_up_sync(FULL,sr,4),  ui=__shfl_up_sync(FULL,si,4);
          if (lane>=4)  { sr += a2r*ur - a2i*ui; si += a2r*ui + a2i*ur; } }
        { float ur=__shfl_up_sync(FULL,sr,8),  ui=__shfl_up_sync(FULL,si,8);
          if (lane>=8)  { sr += a3r*ur - a3i*ui; si += a3r*ui + a3i*ur; } }
        { float ur=__shfl_up_sync(FULL,sr,16), ui=__shfl_up_sync(FULL,si,16);
          if (lane>=16) { sr += a4r*ur - a4i*ui; si += a4r*ui + a4i*ur; } }

        float hr = __shfl_up_sync(FULL, sr, 1);
        float hi = __shfl_up_sync(FULL, si, 1);
        if (lane == 0) { hr = 0.f; hi = 0.f; }

        // lane entry z = h + q*in
        float zr = hr + qr*inr - qi*ini;
        float zi = hi + qr*ini + qi*inr;

        // outputs o_k = c_k + e^k * z  (independent complex FMAs)
        float o1r = c1r + er*zr  - eic*zi, o1i = c1i + er*zi  + eic*zr;
        float o2r = c2r + e2r*zr - e2i*zi, o2i = c2i + e2r*zi + e2i*zr;
        float o3r = c3r + e3r*zr - e3i*zi, o3i = c3i + e3r*zi + e3i*zr;
        float o4r = c4r + e4r*zr - e4i*zi, o4i = c4i + e4r*zi + e4i*zr;

        if (!REV) {
            st_cs4(out_re + n0, make_float4(o1r,o2r,o3r,o4r));
            st_cs4(out_im + n0, make_float4(o1i,o2i,o3i,o4i));
        } else {
            st_cs4(out_re + (TT - 4 - n0), make_float4(o4r,o3r,o2r,o1r));
            st_cs4(out_im + (TT - 4 - n0), make_float4(o4i,o3i,o2i,o1i));
        }

        // advance slice-entry state: in = T + E128*in  (T = inclusive total, lane 31)
        float Tr = __shfl_sync(FULL, sr, 31);
        float Ti = __shfl_sync(FULL, si, 31);
        float nr = Tr + e128r*inr - e128i*ini;
        float ni = Ti + e128r*ini + e128i*inr;
        inr = nr; ini = ni;
    }
}

__global__ void __launch_bounds__(WPB * 32)
kC(const float* __restrict__ audio, float* __restrict__ out)
{
    int lane = threadIdx.x & 31;
    int W = blockIdx.x * WPB + (threadIdx.x >> 5);
    int s = W / NSLICE;
    int j = W - s * NSLICE;
    int dir = s & 1, c = (s >> 1) & 63, b = s >> 7;

    const float* tb = g_ctab[c];
    const float* x = audio + (size_t)b * TT;
    float* base = out + (size_t)b * 4 * CC * TT;

    if (dir == 0) {
        sliceC<false>(x, base + (size_t)c * TT, base + (size_t)(CC + c) * TT,
                      s, j, lane, tb);
    } else {
        sliceC<true >(x, base + (size_t)(2*CC + c) * TT, base + (size_t)(3*CC + c) * TT,
                      s, j, lane, tb);
    }
}

extern "C" void kernel_launch(void* const* d_in, const int* in_sizes, int n_in,
                              void* d_out, int out_size)
{
    const float* audio = (const float*)d_in[0];
    const float* kre   = (const float*)d_in[1];
    const float* kim   = (const float*)d_in[2];
    float* out = (float*)d_out;
    (void)in_sizes; (void)n_in; (void)out_size;

    kprep<<<1, 64>>>(kre, kim);
    kA<<<NBLK, WPB * 32>>>(audio);
    kC<<<NBLK, WPB * 32>>>(audio, out);
}

// round 12
// speedup vs baseline: 1.6270x; 1.0261x over previous
#include <cuda_runtime.h>
#include <cstdint>

// CSpace resonator bank as 1st-order complex IIR, split-scan over time slices.
// 1024 sequences x 25 slices of 1920 samples; warp per slice.
// kA grid = 3200 slice blocks + 1 table block (double ladder -> g_ctab for kC).
// Slice blocks derive their own constants per-warp in float (no dependency).
// Kernel C: fold entry + scan + independent reconstruction, streaming stores.

#define TT 48000
#define CC 64
#define BB 8
#define KLEN 24000
#define NSLICE 25
#define SLEN 1920
#define NITERS 15           // 15 * 128 = 1920
#define NSEQ (BB * CC * 2)  // 1024
#define NWORK (NSEQ * NSLICE) // 25600
#define WPB 8               // warps per block
#define NBLK (NWORK / WPB)  // 3200

__device__ float2 g_tot[NWORK];
// table layout (32 floats per channel):
// [0..7]  e^1..e^4 (re,im)
// [8..17] A_k = E4^(2^k), k=0..4  (E4,E8,E16,E32,E64)
// [18..19] E128   [20..21] E1920   [22..23] g
// [24..31] w0..w3  (w_k = g * e^(3-k))
__device__ float g_ctab[CC][32];

__device__ __forceinline__ void cmulD(double& ar, double& ai, double br, double bi) {
    double t = ar * br - ai * bi;
    ai = ar * bi + ai * br;
    ar = t;
}
__device__ __forceinline__ void cmulF(float& ar, float& ai, float br, float bi) {
    float t = ar * br - ai * bi;
    ai = ar * bi + ai * br;
    ar = t;
}

__device__ void make_tab_double(const float* __restrict__ kre,
                                const float* __restrict__ kim, int c)
{
    double k0r = kre[c * KLEN + 0], k0i = kim[c * KLEN + 0];
    double k1r = kre[c * KLEN + 1], k1i = kim[c * KLEN + 1];
    double inv = 1.0 / (k0r * k0r + k0i * k0i);
    double er = (k1r * k0r + k1i * k0i) * inv;
    double ei = (k1i * k0r - k1r * k0i) * inv;

    double e2r = er, e2i = ei;  cmulD(e2r, e2i, er, ei);
    double e3r = e2r, e3i = e2i; cmulD(e3r, e3i, er, ei);
    double e4r = e2r, e4i = e2i; cmulD(e4r, e4i, e2r, e2i);

    double Ar[6], Ai[6];
    Ar[0] = e4r; Ai[0] = e4i;
    #pragma unroll
    for (int k = 1; k < 6; ++k) { Ar[k] = Ar[k-1]; Ai[k] = Ai[k-1]; cmulD(Ar[k], Ai[k], Ar[k-1], Ai[k-1]); }
    double Cr[4], Ci[4];
    Cr[0] = Ar[5]; Ci[0] = Ai[5];
    #pragma unroll
    for (int k = 1; k < 4; ++k) { Cr[k] = Cr[k-1]; Ci[k] = Ci[k-1]; cmulD(Cr[k], Ci[k], Cr[k-1], Ci[k-1]); }
    double Fr = Cr[0], Fi = Ci[0];
    cmulD(Fr, Fi, Cr[1], Ci[1]);
    cmulD(Fr, Fi, Cr[2], Ci[2]);
    cmulD(Fr, Fi, Cr[3], Ci[3]);

    double w3r = k0r, w3i = k0i;
    double w2r = w3r, w2i = w3i; cmulD(w2r, w2i, er, ei);
    double w1r = w3r, w1i = w3i; cmulD(w1r, w1i, e2r, e2i);
    double w0r = w3r, w0i = w3i; cmulD(w0r, w0i, e3r, e3i);

    float* t = g_ctab[c];
    t[0] = (float)er;  t[1] = (float)ei;
    t[2] = (float)e2r; t[3] = (float)e2i;
    t[4] = (float)e3r; t[5] = (float)e3i;
    t[6] = (float)e4r; t[7] = (float)e4i;
    #pragma unroll
    for (int k = 0; k < 5; ++k) { t[8 + 2*k] = (float)Ar[k]; t[9 + 2*k] = (float)Ai[k]; }
    t[18] = (float)Ar[5]; t[19] = (float)Ai[5];
    t[20] = (float)Fr;    t[21] = (float)Fi;
    t[22] = (float)k0r;   t[23] = (float)k0i;
    t[24] = (float)w0r;   t[25] = (float)w0i;
    t[26] = (float)w1r;   t[27] = (float)w1i;
    t[28] = (float)w2r;   t[29] = (float)w2i;
    t[30] = (float)w3r;   t[31] = (float)w3i;
}

// ---------------- Kernel A: slice totals (per-warp float constants) ----------------
template <bool REV>
__device__ __forceinline__ void sliceA(const float* __restrict__ x, int j, int lane,
                                       int c, int W,
                                       const float* __restrict__ kre,
                                       const float* __restrict__ kim)
{
    const unsigned FULL = 0xFFFFFFFFu;

    // derive constants in float (broadcast loads; no table dependency)
    float k0r = kre[c * KLEN + 0], k0i = kim[c * KLEN + 0];
    float k1r = kre[c * KLEN + 1], k1i = kim[c * KLEN + 1];
    float invd = 1.0f / (k0r * k0r + k0i * k0i);
    float er = (k1r * k0r + k1i * k0i) * invd;
    float ei = (k1i * k0r - k1r * k0i) * invd;

    float e2r = er, e2i = ei;   cmulF(e2r, e2i, er, ei);
    float e4r = e2r, e4i = e2i; cmulF(e4r, e4i, e2r, e2i);
    // A_k = E4^(2^k), k=0..4
    float Afr[5], Afi[5];
    Afr[0] = e4r; Afi[0] = e4i;
    #pragma unroll
    for (int k = 1; k < 5; ++k) { Afr[k] = Afr[k-1]; Afi[k] = Afi[k-1]; cmulF(Afr[k], Afi[k], Afr[k-1], Afi[k-1]); }
    float e128r = Afr[4], e128i = Afi[4]; cmulF(e128r, e128i, Afr[4], Afi[4]);
    // w_k = g * e^(3-k)
    float w3r = k0r, w3i = k0i;
    float w2r = w3r, w2i = w3i; cmulF(w2r, w2i, er, ei);
    float w1r = w2r, w1i = w2i; cmulF(w1r, w1i, er, ei);
    float w0r = w1r, w0i = w1i; cmulF(w0r, w0i, er, ei);

    // lane-local accumulator: A = E128*A + y_i  (y_i = weighted 4-sample partial)
    float Acr = 0.f, Aci = 0.f;
    #pragma unroll 5
    for (int i = 0; i < NITERS; ++i) {
        int n0 = j * SLEN + i * 128 + lane * 4;
        float4 v = REV ? *reinterpret_cast<const float4*>(x + (TT - 4 - n0))
                       : *reinterpret_cast<const float4*>(x + n0);
        float x0, x1, x2, x3;
        if (!REV) { x0=v.x; x1=v.y; x2=v.z; x3=v.w; }
        else      { x0=v.w; x1=v.z; x2=v.y; x3=v.x; }

        float yr = w0r*x0 + w1r*x1 + w2r*x2 + w3r*x3;
        float yi = w0i*x0 + w1i*x1 + w2i*x2 + w3i*x3;

        float nAr = yr + e128r*Acr - e128i*Aci;
        float nAi = yi + e128r*Aci + e128i*Acr;
        Acr = nAr; Aci = nAi;
    }

    // weight = E4^(31-lane); one butterfly reduction of w*A
    float wr = 1.f, wi = 0.f;
    {
        int p = 31 - lane;
        #pragma unroll
        for (int k = 0; k < 5; ++k)
            if ((p >> k) & 1) cmulF(wr, wi, Afr[k], Afi[k]);
    }
    float sr = wr*Acr - wi*Aci;
    float si = wr*Aci + wi*Acr;
    #pragma unroll
    for (int d = 16; d >= 1; d >>= 1) {
        sr += __shfl_xor_sync(FULL, sr, d);
        si += __shfl_xor_sync(FULL, si, d);
    }
    if (lane == 0) g_tot[W] = make_float2(sr, si);
}

__global__ void __launch_bounds__(WPB * 32)
kA(const float* __restrict__ audio,
   const float* __restrict__ kre, const float* __restrict__ kim)
{
    if (blockIdx.x == NBLK) {               // table block for kC
        int c = threadIdx.x;
        if (c < CC) make_tab_double(kre, kim, c);
        return;
    }
    int lane = threadIdx.x & 31;
    int W = blockIdx.x * WPB + (threadIdx.x >> 5);
    int s = W / NSLICE;
    int j = W - s * NSLICE;
    int dir = s & 1, c = (s >> 1) & 63, b = s >> 7;

    const float* x = audio + (size_t)b * TT;
    if (dir == 0) sliceA<false>(x, j, lane, c, W, kre, kim);
    else          sliceA<true >(x, j, lane, c, W, kre, kim);
}

// ---------------- Kernel C: outputs (R8/R11 form) ----------------
__device__ __forceinline__ void st_cs4(float* p, float4 v) {
    asm volatile("st.global.cs.v4.f32 [%0], {%1,%2,%3,%4};"
                 :: "l"(p), "f"(v.x), "f"(v.y), "f"(v.z), "f"(v.w) : "memory");
}

template <bool REV>
__device__ __forceinline__ void sliceC(const float* __restrict__ x,
                                       float* __restrict__ out_re,
                                       float* __restrict__ out_im,
                                       int s, int j, int lane,
                                       const float* __restrict__ tb)
{
    const unsigned FULL = 0xFFFFFFFFu;
    const float er  = tb[0],  eic = tb[1];
    const float e2r = tb[2],  e2i = tb[3];
    const float e3r = tb[4],  e3i = tb[5];
    const float e4r = tb[6],  e4i = tb[7];
    const float a0r = tb[8],  a0i = tb[9];
    const float a1r = tb[10], a1i = tb[11];
    const float a2r = tb[12], a2i = tb[13];
    const float a3r = tb[14], a3i = tb[15];
    const float a4r = tb[16], a4i = tb[17];
    const float e128r = tb[18], e128i = tb[19];
    const float f19r  = tb[20], f19i  = tb[21];
    const float gr = tb[22], gi = tb[23];

    // q = E4^lane
    float qr = 1.f, qi = 0.f;
    #pragma unroll
    for (int k = 0; k < 5; ++k)
        if ((lane >> k) & 1) {
            float ar = tb[8 + 2*k], ai = tb[9 + 2*k];
            float nr = qr*ar - qi*ai, ni = qr*ai + qi*ar;
            qr = nr; qi = ni;
        }

    // fold predecessor slice totals -> entry state (uniform loads, all lanes)
    float inr = 0.f, ini = 0.f;
    const float2* tot = &g_tot[s * NSLICE];
    for (int t = 0; t < j; ++t) {
        float2 v = tot[t];
        float nr = v.x + f19r*inr - f19i*ini;
        float ni = v.y + f19r*ini + f19i*inr;
        inr = nr; ini = ni;
    }

    #pragma unroll 3
    for (int i = 0; i < NITERS; ++i) {
        int n0 = j * SLEN + i * 128 + lane * 4;
        float4 v = REV ? *reinterpret_cast<const float4*>(x + (TT - 4 - n0))
                       : *reinterpret_cast<const float4*>(x + n0);
        float x0, x1, x2, x3;
        if (!REV) { x0=v.x; x1=v.y; x2=v.z; x3=v.w; }
        else      { x0=v.w; x1=v.z; x2=v.y; x3=v.x; }

        // local partials from zero (kept for output reconstruction)
        float c1r = gr*x0, c1i = gi*x0;
        float c2r = er*c1r - eic*c1i + gr*x1, c2i = er*c1i + eic*c1r + gi*x1;
        float c3r = er*c2r - eic*c2i + gr*x2, c3i = er*c2i + eic*c2r + gi*x2;
        float c4r = er*c3r - eic*c3i + gr*x3, c4i = er*c3i + eic*c3r + gi*x3;

        // warp inclusive scan of c4 with ratio E4
        float sr = c4r, si = c4i;
        { float ur=__shfl_up_sync(FULL,sr,1),  ui=__shfl_up_sync(FULL,si,1);
          if (lane>=1)  { sr += a0r*ur - a0i*ui; si += a0r*ui + a0i*ur; } }
        { float ur=__shfl_up_sync(FULL,sr,2),  ui=__shfl_up_sync(FULL,si,2);
          if (lane>=2)  { sr += a1r*ur - a1i*ui; si += a1r*ui + a1i*ur; } }
        { float ur=__shfl_up_sync(FULL,sr,4),  ui=__shfl_up_sync(FULL,si,4);
          if (lane>=4)  { sr += a2r*ur - a2i*ui; si += a2r*ui + a2i*ur; } }
        { float ur=__shfl_up_sync(FULL,sr,8),  ui=__shfl_up_sync(FULL,si,8);
          if (lane>=8)  { sr += a3r*ur - a3i*ui; si += a3r*ui + a3i*ur; } }
        { float ur=__shfl_up_sync(FULL,sr,16), ui=__shfl_up_sync(FULL,si,16);
          if (lane>=16) { sr += a4r*ur - a4i*ui; si += a4r*ui + a4i*ur; } }

        float hr = __shfl_up_sync(FULL, sr, 1);
        float hi = __shfl_up_sync(FULL, si, 1);
        if (lane == 0) { hr = 0.f; hi = 0.f; }

        // lane entry z = h + q*in
        float zr = hr + qr*inr - qi*ini;
        float zi = hi + qr*ini + qi*inr;

        // outputs o_k = c_k + e^k * z  (independent complex FMAs)
        float o1r = c1r + er*zr  - eic*zi, o1i = c1i + er*zi  + eic*zr;
        float o2r = c2r + e2r*zr - e2i*zi, o2i = c2i + e2r*zi + e2i*zr;
        float o3r = c3r + e3r*zr - e3i*zi, o3i = c3i + e3r*zi + e3i*zr;
        float o4r = c4r + e4r*zr - e4i*zi, o4i = c4i + e4r*zi + e4i*zr;

        if (!REV) {
            st_cs4(out_re + n0, make_float4(o1r,o2r,o3r,o4r));
            st_cs4(out_im + n0, make_float4(o1i,o2i,o3i,o4i));
        } else {
            st_cs4(out_re + (TT - 4 - n0), make_float4(o4r,o3r,o2r,o1r));
            st_cs4(out_im + (TT - 4 - n0), make_float4(o4i,o3i,o2i,o1i));
        }

        // advance slice-entry state: in = T + E128*in  (T = inclusive total, lane 31)
        float Tr = __shfl_sync(FULL, sr, 31);
        float Ti = __shfl_sync(FULL, si, 31);
        float nr = Tr + e128r*inr - e128i*ini;
        float ni = Ti + e128r*ini + e128i*inr;
        inr = nr; ini = ni;
    }
}

__global__ void __launch_bounds__(WPB * 32)
kC(const float* __restrict__ audio, float* __restrict__ out)
{
    int lane = threadIdx.x & 31;
    int W = blockIdx.x * WPB + (threadIdx.x >> 5);
    int s = W / NSLICE;
    int j = W - s * NSLICE;
    int dir = s & 1, c = (s >> 1) & 63, b = s >> 7;

    const float* tb = g_ctab[c];
    const float* x = audio + (size_t)b * TT;
    float* base = out + (size_t)b * 4 * CC * TT;

    if (dir == 0) {
        sliceC<false>(x, base + (size_t)c * TT, base + (size_t)(CC + c) * TT,
                      s, j, lane, tb);
    } else {
        sliceC<true >(x, base + (size_t)(2*CC + c) * TT, base + (size_t)(3*CC + c) * TT,
                      s, j, lane, tb);
    }
}

extern "C" void kernel_launch(void* const* d_in, const int* in_sizes, int n_in,
                              void* d_out, int out_size)
{
    const float* audio = (const float*)d_in[0];
    const float* kre   = (const float*)d_in[1];
    const float* kim   = (const float*)d_in[2];
    float* out = (float*)d_out;
    (void)in_sizes; (void)n_in; (void)out_size;

    kA<<<NBLK + 1, WPB * 32>>>(audio, kre, kim);
    kC<<<NBLK, WPB * 32>>>(audio, out);
}

// round 13
// speedup vs baseline: 1.6357x; 1.0053x over previous
#include <cuda_runtime.h>
#include <cstdint>

// CSpace resonator bank as 1st-order complex IIR, split-scan over time slices.
// 1024 sequences x 25 slices of 1920 samples; warp per slice.
// kA grid = 3200 slice blocks + 1 table block (double ladder -> g_ctab for kC).
// Slice blocks derive their own constants per-warp in float (no dependency).
// Kernel C: fold entry + scan + independent reconstruction, streaming stores.
// R13: kC reg-capped to 64 (__launch_bounds__(256,4)) for 4 blocks/SM occupancy.

#define TT 48000
#define CC 64
#define BB 8
#define KLEN 24000
#define NSLICE 25
#define SLEN 1920
#define NITERS 15           // 15 * 128 = 1920
#define NSEQ (BB * CC * 2)  // 1024
#define NWORK (NSEQ * NSLICE) // 25600
#define WPB 8               // warps per block
#define NBLK (NWORK / WPB)  // 3200

__device__ float2 g_tot[NWORK];
// table layout (32 floats per channel):
// [0..7]  e^1..e^4 (re,im)
// [8..17] A_k = E4^(2^k), k=0..4  (E4,E8,E16,E32,E64)
// [18..19] E128   [20..21] E1920   [22..23] g
// [24..31] w0..w3  (w_k = g * e^(3-k))
__device__ float g_ctab[CC][32];

__device__ __forceinline__ void cmulD(double& ar, double& ai, double br, double bi) {
    double t = ar * br - ai * bi;
    ai = ar * bi + ai * br;
    ar = t;
}
__device__ __forceinline__ void cmulF(float& ar, float& ai, float br, float bi) {
    float t = ar * br - ai * bi;
    ai = ar * bi + ai * br;
    ar = t;
}

__device__ void make_tab_double(const float* __restrict__ kre,
                                const float* __restrict__ kim, int c)
{
    double k0r = kre[c * KLEN + 0], k0i = kim[c * KLEN + 0];
    double k1r = kre[c * KLEN + 1], k1i = kim[c * KLEN + 1];
    double inv = 1.0 / (k0r * k0r + k0i * k0i);
    double er = (k1r * k0r + k1i * k0i) * inv;
    double ei = (k1i * k0r - k1r * k0i) * inv;

    double e2r = er, e2i = ei;  cmulD(e2r, e2i, er, ei);
    double e3r = e2r, e3i = e2i; cmulD(e3r, e3i, er, ei);
    double e4r = e2r, e4i = e2i; cmulD(e4r, e4i, e2r, e2i);

    double Ar[6], Ai[6];
    Ar[0] = e4r; Ai[0] = e4i;
    #pragma unroll
    for (int k = 1; k < 6; ++k) { Ar[k] = Ar[k-1]; Ai[k] = Ai[k-1]; cmulD(Ar[k], Ai[k], Ar[k-1], Ai[k-1]); }
    double Cr[4], Ci[4];
    Cr[0] = Ar[5]; Ci[0] = Ai[5];
    #pragma unroll
    for (int k = 1; k < 4; ++k) { Cr[k] = Cr[k-1]; Ci[k] = Ci[k-1]; cmulD(Cr[k], Ci[k], Cr[k-1], Ci[k-1]); }
    double Fr = Cr[0], Fi = Ci[0];
    cmulD(Fr, Fi, Cr[1], Ci[1]);
    cmulD(Fr, Fi, Cr[2], Ci[2]);
    cmulD(Fr, Fi, Cr[3], Ci[3]);

    double w3r = k0r, w3i = k0i;
    double w2r = w3r, w2i = w3i; cmulD(w2r, w2i, er, ei);
    double w1r = w3r, w1i = w3i; cmulD(w1r, w1i, e2r, e2i);
    double w0r = w3r, w0i = w3i; cmulD(w0r, w0i, e3r, e3i);

    float* t = g_ctab[c];
    t[0] = (float)er;  t[1] = (float)ei;
    t[2] = (float)e2r; t[3] = (float)e2i;
    t[4] = (float)e3r; t[5] = (float)e3i;
    t[6] = (float)e4r; t[7] = (float)e4i;
    #pragma unroll
    for (int k = 0; k < 5; ++k) { t[8 + 2*k] = (float)Ar[k]; t[9 + 2*k] = (float)Ai[k]; }
    t[18] = (float)Ar[5]; t[19] = (float)Ai[5];
    t[20] = (float)Fr;    t[21] = (float)Fi;
    t[22] = (float)k0r;   t[23] = (float)k0i;
    t[24] = (float)w0r;   t[25] = (float)w0i;
    t[26] = (float)w1r;   t[27] = (float)w1i;
    t[28] = (float)w2r;   t[29] = (float)w2i;
    t[30] = (float)w3r;   t[31] = (float)w3i;
}

// ---------------- Kernel A: slice totals (per-warp float constants) ----------------
template <bool REV>
__device__ __forceinline__ void sliceA(const float* __restrict__ x, int j, int lane,
                                       int c, int W,
                                       const float* __restrict__ kre,
                                       const float* __restrict__ kim)
{
    const unsigned FULL = 0xFFFFFFFFu;

    // derive constants in float (broadcast loads; no table dependency)
    float k0r = kre[c * KLEN + 0], k0i = kim[c * KLEN + 0];
    float k1r = kre[c * KLEN + 1], k1i = kim[c * KLEN + 1];
    float invd = 1.0f / (k0r * k0r + k0i * k0i);
    float er = (k1r * k0r + k1i * k0i) * invd;
    float ei = (k1i * k0r - k1r * k0i) * invd;

    float e2r = er, e2i = ei;   cmulF(e2r, e2i, er, ei);
    float e4r = e2r, e4i = e2i; cmulF(e4r, e4i, e2r, e2i);
    // A_k = E4^(2^k), k=0..4
    float Afr[5], Afi[5];
    Afr[0] = e4r; Afi[0] = e4i;
    #pragma unroll
    for (int k = 1; k < 5; ++k) { Afr[k] = Afr[k-1]; Afi[k] = Afi[k-1]; cmulF(Afr[k], Afi[k], Afr[k-1], Afi[k-1]); }
    float e128r = Afr[4], e128i = Afi[4]; cmulF(e128r, e128i, Afr[4], Afi[4]);
    // w_k = g * e^(3-k)
    float w3r = k0r, w3i = k0i;
    float w2r = w3r, w2i = w3i; cmulF(w2r, w2i, er, ei);
    float w1r = w2r, w1i = w2i; cmulF(w1r, w1i, er, ei);
    float w0r = w1r, w0i = w1i; cmulF(w0r, w0i, er, ei);

    // lane-local accumulator: A = E128*A + y_i  (y_i = weighted 4-sample partial)
    float Acr = 0.f, Aci = 0.f;
    #pragma unroll 5
    for (int i = 0; i < NITERS; ++i) {
        int n0 = j * SLEN + i * 128 + lane * 4;
        float4 v = REV ? *reinterpret_cast<const float4*>(x + (TT - 4 - n0))
                       : *reinterpret_cast<const float4*>(x + n0);
        float x0, x1, x2, x3;
        if (!REV) { x0=v.x; x1=v.y; x2=v.z; x3=v.w; }
        else      { x0=v.w; x1=v.z; x2=v.y; x3=v.x; }

        float yr = w0r*x0 + w1r*x1 + w2r*x2 + w3r*x3;
        float yi = w0i*x0 + w1i*x1 + w2i*x2 + w3i*x3;

        float nAr = yr + e128r*Acr - e128i*Aci;
        float nAi = yi + e128r*Aci + e128i*Acr;
        Acr = nAr; Aci = nAi;
    }

    // weight = E4^(31-lane); one butterfly reduction of w*A
    float wr = 1.f, wi = 0.f;
    {
        int p = 31 - lane;
        #pragma unroll
        for (int k = 0; k < 5; ++k)
            if ((p >> k) & 1) cmulF(wr, wi, Afr[k], Afi[k]);
    }
    float sr = wr*Acr - wi*Aci;
    float si = wr*Aci + wi*Acr;
    #pragma unroll
    for (int d = 16; d >= 1; d >>= 1) {
        sr += __shfl_xor_sync(FULL, sr, d);
        si += __shfl_xor_sync(FULL, si, d);
    }
    if (lane == 0) g_tot[W] = make_float2(sr, si);
}

__global__ void __launch_bounds__(WPB * 32)
kA(const float* __restrict__ audio,
   const float* __restrict__ kre, const float* __restrict__ kim)
{
    if (blockIdx.x == NBLK) {               // table block for kC
        int c = threadIdx.x;
        if (c < CC) make_tab_double(kre, kim, c);
        return;
    }
    int lane = threadIdx.x & 31;
    int W = blockIdx.x * WPB + (threadIdx.x >> 5);
    int s = W / NSLICE;
    int j = W - s * NSLICE;
    int dir = s & 1, c = (s >> 1) & 63, b = s >> 7;

    const float* x = audio + (size_t)b * TT;
    if (dir == 0) sliceA<false>(x, j, lane, c, W, kre, kim);
    else          sliceA<true >(x, j, lane, c, W, kre, kim);
}

// ---------------- Kernel C: outputs ----------------
__device__ __forceinline__ void st_cs4(float* p, float4 v) {
    asm volatile("st.global.cs.v4.f32 [%0], {%1,%2,%3,%4};"
                 :: "l"(p), "f"(v.x), "f"(v.y), "f"(v.z), "f"(v.w) : "memory");
}

template <bool REV>
__device__ __forceinline__ void sliceC(const float* __restrict__ x,
                                       float* __restrict__ out_re,
                                       float* __restrict__ out_im,
                                       int s, int j, int lane,
                                       const float* __restrict__ tb)
{
    const unsigned FULL = 0xFFFFFFFFu;
    const float er  = tb[0],  eic = tb[1];
    const float e2r = tb[2],  e2i = tb[3];
    const float e3r = tb[4],  e3i = tb[5];
    const float e4r = tb[6],  e4i = tb[7];
    const float a0r = tb[8],  a0i = tb[9];
    const float a1r = tb[10], a1i = tb[11];
    const float a2r = tb[12], a2i = tb[13];
    const float a3r = tb[14], a3i = tb[15];
    const float a4r = tb[16], a4i = tb[17];
    const float e128r = tb[18], e128i = tb[19];
    const float f19r  = tb[20], f19i  = tb[21];
    const float gr = tb[22], gi = tb[23];

    // q = E4^lane
    float qr = 1.f, qi = 0.f;
    #pragma unroll
    for (int k = 0; k < 5; ++k)
        if ((lane >> k) & 1) {
            float ar = tb[8 + 2*k], ai = tb[9 + 2*k];
            float nr = qr*ar - qi*ai, ni = qr*ai + qi*ar;
            qr = nr; qi = ni;
        }

    // fold predecessor slice totals -> entry state (uniform loads, all lanes)
    float inr = 0.f, ini = 0.f;
    const float2* tot = &g_tot[s * NSLICE];
    for (int t = 0; t < j; ++t) {
        float2 v = tot[t];
        float nr = v.x + f19r*inr - f19i*ini;
        float ni = v.y + f19r*ini + f19i*inr;
        inr = nr; ini = ni;
    }

    #pragma unroll 3
    for (int i = 0; i < NITERS; ++i) {
        int n0 = j * SLEN + i * 128 + lane * 4;
        float4 v = REV ? *reinterpret_cast<const float4*>(x + (TT - 4 - n0))
                       : *reinterpret_cast<const float4*>(x + n0);
        float x0, x1, x2, x3;
        if (!REV) { x0=v.x; x1=v.y; x2=v.z; x3=v.w; }
        else      { x0=v.w; x1=v.z; x2=v.y; x3=v.x; }

        // local partials from zero (kept for output reconstruction)
        float c1r = gr*x0, c1i = gi*x0;
        float c2r = er*c1r - eic*c1i + gr*x1, c2i = er*c1i + eic*c1r + gi*x1;
        float c3r = er*c2r - eic*c2i + gr*x2, c3i = er*c2i + eic*c2r + gi*x2;
        float c4r = er*c3r - eic*c3i + gr*x3, c4i = er*c3i + eic*c3r + gi*x3;

        // warp inclusive scan of c4 with ratio E4
        float sr = c4r, si = c4i;
        { float ur=__shfl_up_sync(FULL,sr,1),  ui=__shfl_up_sync(FULL,si,1);
          if (lane>=1)  { sr += a0r*ur - a0i*ui; si += a0r*ui + a0i*ur; } }
        { float ur=__shfl_up_sync(FULL,sr,2),  ui=__shfl_up_sync(FULL,si,2);
          if (lane>=2)  { sr += a1r*ur - a1i*ui; si += a1r*ui + a1i*ur; } }
        { float ur=__shfl_up_sync(FULL,sr,4),  ui=__shfl_up_sync(FULL,si,4);
          if (lane>=4)  { sr += a2r*ur - a2i*ui; si += a2r*ui + a2i*ur; } }
        { float ur=__shfl_up_sync(FULL,sr,8),  ui=__shfl_up_sync(FULL,si,8);
          if (lane>=8)  { sr += a3r*ur - a3i*ui; si += a3r*ui + a3i*ur; } }
        { float ur=__shfl_up_sync(FULL,sr,16), ui=__shfl_up_sync(FULL,si,16);
          if (lane>=16) { sr += a4r*ur - a4i*ui; si += a4r*ui + a4i*ur; } }

        float hr = __shfl_up_sync(FULL, sr, 1);
        float hi = __shfl_up_sync(FULL, si, 1);
        if (lane == 0) { hr = 0.f; hi = 0.f; }

        // lane entry z = h + q*in
        float zr = hr + qr*inr - qi*ini;
        float zi = hi + qr*ini + qi*inr;

        // outputs o_k = c_k + e^k * z  (independent complex FMAs)
        float o1r = c1r + er*zr  - eic*zi, o1i = c1i + er*zi  + eic*zr;
        float o2r = c2r + e2r*zr - e2i*zi, o2i = c2i + e2r*zi + e2i*zr;
        float o3r = c3r + e3r*zr - e3i*zi, o3i = c3i + e3r*zi + e3i*zr;
        float o4r = c4r + e4r*zr - e4i*zi, o4i = c4i + e4r*zi + e4i*zr;

        if (!REV) {
            st_cs4(out_re + n0, make_float4(o1r,o2r,o3r,o4r));
            st_cs4(out_im + n0, make_float4(o1i,o2i,o3i,o4i));
        } else {
            st_cs4(out_re + (TT - 4 - n0), make_float4(o4r,o3r,o2r,o1r));
            st_cs4(out_im + (TT - 4 - n0), make_float4(o4i,o3i,o2i,o1i));
        }

        // advance slice-entry state: in = T + E128*in  (T = inclusive total, lane 31)
        float Tr = __shfl_sync(FULL, sr, 31);
        float Ti = __shfl_sync(FULL, si, 31);
        float nr = Tr + e128r*inr - e128i*ini;
        float ni = Ti + e128r*ini + e128i*inr;
        inr = nr; ini = ni;
    }
}

__global__ void __launch_bounds__(WPB * 32, 4)
kC(const float* __restrict__ audio, float* __restrict__ out)
{
    int lane = threadIdx.x & 31;
    int W = blockIdx.x * WPB + (threadIdx.x >> 5);
    int s = W / NSLICE;
    int j = W - s * NSLICE;
    int dir = s & 1, c = (s >> 1) & 63, b = s >> 7;

    const float* tb = g_ctab[c];
    const float* x = audio + (size_t)b * TT;
    float* base = out + (size_t)b * 4 * CC * TT;

    if (dir == 0) {
        sliceC<false>(x, base + (size_t)c * TT, base + (size_t)(CC + c) * TT,
                      s, j, lane, tb);
    } else {
        sliceC<true >(x, base + (size_t)(2*CC + c) * TT, base + (size_t)(3*CC + c) * TT,
                      s, j, lane, tb);
    }
}

extern "C" void kernel_launch(void* const* d_in, const int* in_sizes, int n_in,
                              void* d_out, int out_size)
{
    const float* audio = (const float*)d_in[0];
    const float* kre   = (const float*)d_in[1];
    const float* kim   = (const float*)d_in[2];
    float* out = (float*)d_out;
    (void)in_sizes; (void)n_in; (void)out_size;

    kA<<<NBLK + 1, WPB * 32>>>(audio, kre, kim);
    kC<<<NBLK, WPB * 32>>>(audio, out);
}